// round 12
// baseline (speedup 1.0000x reference)
#include <cuda_runtime.h>

#define BB    64
#define TC    288
#define TF    12
#define LMAX  300
#define DD    16
#define HH    4
#define HDIM  4
#define DFF   64
#define NLAY  4
#define FULL  0xffffffffu

// ---------------- device scratch ----------------
__device__ float g_x  [BB*TC*DD];
__device__ float g_q  [BB*TC*DD];
__device__ float g_att[BB*TC*DD];
__device__ float g_K  [NLAY*BB*HH*LMAX*HDIM];
__device__ float g_V  [NLAY*BB*HH*LMAX*HDIM];
__device__ float g_WqT[NLAY*768];            // [l][e][c]   e*48+c
__device__ float g_WoT[NLAY*256];            // [l][e][d]   e*16+d
__device__ float g_W1T[NLAY*1024];           // [l][e][j]   e*64+j
__device__ float g_W2T[NLAY*1024];           // [l][j][d]   j*16+d

__device__ __forceinline__ int kidx(int l,int b,int h,int p,int d){
    return (((l*BB+b)*HH+h)*LMAX+p)*HDIM+d;
}

__device__ __forceinline__ float gsum16f(float v){
    v += __shfl_xor_sync(FULL, v, 8, 16);
    v += __shfl_xor_sync(FULL, v, 4, 16);
    v += __shfl_xor_sync(FULL, v, 2, 16);
    v += __shfl_xor_sync(FULL, v, 1, 16);
    return v;
}
__device__ __forceinline__ float lnorm16s(float v, float g, float b){
    float s1 = v, s2 = v*v;
    #pragma unroll
    for (int o=8;o>0;o>>=1){
        s1 += __shfl_xor_sync(FULL, s1, o, 16);
        s2 += __shfl_xor_sync(FULL, s2, o, 16);
    }
    float mu  = s1 * 0.0625f;
    float var = fmaf(s2, 0.0625f, -mu*mu);
    return (v - mu) * rsqrtf(var + 1e-5f) * g + b;
}

// ---------------- weight transpose prep ----------------
__global__ void prep_kernel(const float* __restrict__ Wqkv, const float* __restrict__ Wo,
                            const float* __restrict__ fW1,  const float* __restrict__ fW2){
    int tid = blockIdx.x*blockDim.x + threadIdx.x;
    int str = gridDim.x*blockDim.x;
    for (int i=tid;i<NLAY*768;i+=str){ int l=i/768, r=i%768, e=r/48, c=r%48;
        g_WqT[i] = Wqkv[(l*48+c)*16+e]; }
    for (int i=tid;i<NLAY*256;i+=str){ int l=i/256, r=i%256, e=r/16, d=r%16;
        g_WoT[i] = Wo[(l*16+d)*16+e]; }
    for (int i=tid;i<NLAY*1024;i+=str){ int l=i/1024, r=i%1024, e=r/64, j=r%64;
        g_W1T[i] = fW1[(l*64+j)*16+e]; }
    for (int i=tid;i<NLAY*1024;i+=str){ int l=i/1024, r=i%1024, j=r/16, d=r%16;
        g_W2T[i] = fW2[(l*16+d)*64+j]; }
}

// ---------------- fusion + layer-0 QKV ----------------
__global__ void fuse_kernel(const float* __restrict__ b1, const float* __restrict__ b2,
                            const float* __restrict__ b3, const float* __restrict__ fW,
                            const float* __restrict__ fb, const float* __restrict__ pe,
                            const float* __restrict__ bqkv){
    __shared__ __align__(16) float WfT[768];
    __shared__ __align__(16) float WT[768];
    __shared__ float fbs[16], bs[48];
    int tid = threadIdx.x;       // 256
    for (int i=tid;i<768;i+=256){ int e=i>>4, d=i&15; WfT[i] = fW[d*48+e]; }
    for (int i=tid;i<768;i+=256) WT[i] = g_WqT[i];
    if (tid<16) fbs[tid] = fb[tid];
    if (tid<48) bs[tid]  = bqkv[tid];
    __syncthreads();
    int idx = blockIdx.x*256 + tid;
    int row = idx >> 4, d = idx & 15;
    int i   = row % TC;
    int b   = row / TC;
    const float* r1 = b1 + row*16;
    const float* r2 = b2 + row*16;
    const float* r3 = b3 + row*16;
    float acc = fbs[d];
    #pragma unroll
    for (int e=0;e<16;e++) acc = fmaf(r1[e], WfT[e*16+d],      acc);
    #pragma unroll
    for (int e=0;e<16;e++) acc = fmaf(r2[e], WfT[(16+e)*16+d], acc);
    #pragma unroll
    for (int e=0;e<16;e++) acc = fmaf(r3[e], WfT[(32+e)*16+d], acc);
    acc += pe[i*16+d];
    g_x[idx] = acc;
    float aq=bs[d], ak=bs[16+d], av=bs[32+d];
    #pragma unroll
    for (int e=0;e<16;e++){
        float xe = __shfl_sync(FULL, acc, e, 16);
        aq = fmaf(xe, WT[e*48+d],    aq);
        ak = fmaf(xe, WT[e*48+16+d], ak);
        av = fmaf(xe, WT[e*48+32+d], av);
    }
    g_q[row*16+d] = aq;
    g_K[kidx(0,b,d>>2,i,d&3)] = ak;
    g_V[kidx(0,b,d>>2,i,d&3)] = av;
}

// ---------------- prefill attention: 2 threads per row (key split) ----------------
__global__ void attn_kernel(int l){
    __shared__ float4 ks4[TC], vs4[TC];
    int b = blockIdx.x >> 2, h = blockIdx.x & 3;
    int tid = threadIdx.x;   // 576
    const float4* Kb = (const float4*)(g_K + kidx(l,b,h,0,0));
    const float4* Vb = (const float4*)(g_V + kidx(l,b,h,0,0));
    for (int i=tid;i<TC;i+=576){ ks4[i]=Kb[i]; vs4[i]=Vb[i]; }
    __syncthreads();
    int i = tid >> 1;        // row
    int u = tid & 1;         // key-parity half
    float4 qv = ((const float4*)g_q)[(b*TC+i)*4 + h];
    float q0=qv.x, q1=qv.y, q2=qv.z, q3=qv.w;
    float s=0.f, o0=0.f, o1=0.f, o2=0.f, o3=0.f;
    int jend = min(i|15, TC-1);          // warp-uniform (16 rows per warp)
    for (int j=u;j<=jend;j+=2){
        float4 k4 = ks4[j];
        float sc = (k4.x*q0 + k4.y*q1 + k4.z*q2 + k4.w*q3) * 0.5f;
        float p  = __expf(sc);
        p = (j <= i) ? p : 0.f;
        float4 v4 = vs4[j];
        s += p;
        o0 = fmaf(p, v4.x, o0); o1 = fmaf(p, v4.y, o1);
        o2 = fmaf(p, v4.z, o2); o3 = fmaf(p, v4.w, o3);
    }
    s  += __shfl_xor_sync(FULL, s,  1);
    o0 += __shfl_xor_sync(FULL, o0, 1);
    o1 += __shfl_xor_sync(FULL, o1, 1);
    o2 += __shfl_xor_sync(FULL, o2, 1);
    o3 += __shfl_xor_sync(FULL, o3, 1);
    if (u==0){
        float inv = 1.0f/s;
        float4 r; r.x=o0*inv; r.y=o1*inv; r.z=o2*inv; r.w=o3*inv;
        ((float4*)g_att)[(b*TC+i)*4 + h] = r;
    }
}

// ---------------- post: thread-per-row, h[64] in registers for deep ILP ----------------
__global__ void __launch_bounds__(128,1) post_kernel(
    int l, const float* __restrict__ bo, const float* __restrict__ crossb,
    const float* __restrict__ l1g, const float* __restrict__ l1b,
    const float* __restrict__ l2g, const float* __restrict__ l2b,
    const float* __restrict__ l3g, const float* __restrict__ l3b,
    const float* __restrict__ fb1, const float* __restrict__ fb2,
    const float* __restrict__ bqkv){
    __shared__ __align__(16) float WoT[256], W1T[1024], W2T[1024], WTn[768];
    __shared__ float bos[16], cbs[16], g1[16], bb1[16], g2[16], bb2[16], g3[16], bb3[16];
    __shared__ float fb1s[64], fb2s[16], bsn[48];
    int tid = threadIdx.x;   // 128
    for (int i=tid;i<256;i+=128)  WoT[i] = g_WoT[l*256+i];
    for (int i=tid;i<1024;i+=128) W1T[i] = g_W1T[l*1024+i];
    for (int i=tid;i<1024;i+=128) W2T[i] = g_W2T[l*1024+i];
    if (l < NLAY-1){
        for (int i=tid;i<768;i+=128) WTn[i] = g_WqT[(l+1)*768+i];
        if (tid<48) bsn[tid] = bqkv[(l+1)*48+tid];
    }
    if (tid<16){
        bos[tid]=bo[l*16+tid]; cbs[tid]=crossb[l*16+tid];
        g1[tid]=l1g[l*16+tid]; bb1[tid]=l1b[l*16+tid];
        g2[tid]=l2g[l*16+tid]; bb2[tid]=l2b[l*16+tid];
        g3[tid]=l3g[l*16+tid]; bb3[tid]=l3b[l*16+tid];
        fb2s[tid]=fb2[l*16+tid];
    }
    if (tid<64) fb1s[tid]=fb1[l*64+tid];
    __syncthreads();
    int row = blockIdx.x*128 + tid;          // 18432 rows, grid 144
    int b = row / TC, i = row % TC;

    float a[16], att[16];
    {
        const float4* xr = (const float4*)(g_x + row*16);
        const float4* ar = (const float4*)(g_att + row*16);
        #pragma unroll
        for (int k=0;k<4;k++){
            float4 xv = xr[k], av = ar[k];
            a[k*4+0]=xv.x; a[k*4+1]=xv.y; a[k*4+2]=xv.z; a[k*4+3]=xv.w;
            att[k*4+0]=av.x; att[k*4+1]=av.y; att[k*4+2]=av.z; att[k*4+3]=av.w;
        }
    }
    #pragma unroll
    for (int d=0;d<16;d++) a[d] += bos[d];
    #pragma unroll
    for (int e=0;e<16;e++){
        float ae = att[e];
        #pragma unroll
        for (int k=0;k<4;k++){
            float4 w = *(const float4*)&WoT[e*16+k*4];
            a[k*4+0]=fmaf(ae,w.x,a[k*4+0]); a[k*4+1]=fmaf(ae,w.y,a[k*4+1]);
            a[k*4+2]=fmaf(ae,w.z,a[k*4+2]); a[k*4+3]=fmaf(ae,w.w,a[k*4+3]);
        }
    }
    // LN1 + cross + LN2 (serial, registers)
    {
        float s1=0.f,s2=0.f;
        #pragma unroll
        for (int d=0;d<16;d++){ s1+=a[d]; s2=fmaf(a[d],a[d],s2); }
        float mu=s1*0.0625f, rstd=rsqrtf(fmaf(s2,0.0625f,-mu*mu)+1e-5f);
        #pragma unroll
        for (int d=0;d<16;d++) a[d] = (a[d]-mu)*rstd*g1[d] + bb1[d] + cbs[d];
        s1=0.f; s2=0.f;
        #pragma unroll
        for (int d=0;d<16;d++){ s1+=a[d]; s2=fmaf(a[d],a[d],s2); }
        mu=s1*0.0625f; rstd=rsqrtf(fmaf(s2,0.0625f,-mu*mu)+1e-5f);
        #pragma unroll
        for (int d=0;d<16;d++) a[d] = (a[d]-mu)*rstd*g2[d] + bb2[d];
    }
    // FFN1: full h[64] in registers, 64 independent chains
    float h[64];
    #pragma unroll
    for (int j=0;j<64;j++) h[j] = fb1s[j];
    #pragma unroll
    for (int e=0;e<16;e++){
        float ze = a[e];
        #pragma unroll
        for (int j4=0;j4<16;j4++){
            float4 w = *(const float4*)&W1T[e*64 + j4*4];
            h[j4*4+0]=fmaf(ze,w.x,h[j4*4+0]); h[j4*4+1]=fmaf(ze,w.y,h[j4*4+1]);
            h[j4*4+2]=fmaf(ze,w.z,h[j4*4+2]); h[j4*4+3]=fmaf(ze,w.w,h[j4*4+3]);
        }
    }
    #pragma unroll
    for (int j=0;j<64;j++) h[j] = fmaxf(h[j], 0.f);
    // FFN2: 64 independent j-blocks into 16 accumulators
    float f[16];
    #pragma unroll
    for (int d=0;d<16;d++) f[d] = fb2s[d] + a[d];
    #pragma unroll
    for (int j=0;j<64;j++){
        float hj = h[j];
        #pragma unroll
        for (int k=0;k<4;k++){
            float4 w = *(const float4*)&W2T[j*16+k*4];
            f[k*4+0]=fmaf(hj,w.x,f[k*4+0]); f[k*4+1]=fmaf(hj,w.y,f[k*4+1]);
            f[k*4+2]=fmaf(hj,w.z,f[k*4+2]); f[k*4+3]=fmaf(hj,w.w,f[k*4+3]);
        }
    }
    // LN3
    {
        float s1=0.f,s2=0.f;
        #pragma unroll
        for (int d=0;d<16;d++){ s1+=f[d]; s2=fmaf(f[d],f[d],s2); }
        float mu=s1*0.0625f, rstd=rsqrtf(fmaf(s2,0.0625f,-mu*mu)+1e-5f);
        #pragma unroll
        for (int d=0;d<16;d++) f[d] = (f[d]-mu)*rstd*g3[d] + bb3[d];
    }
    {
        float4* xw = (float4*)(g_x + row*16);
        #pragma unroll
        for (int k=0;k<4;k++) xw[k] = make_float4(f[k*4+0],f[k*4+1],f[k*4+2],f[k*4+3]);
    }
    if (l < NLAY-1){
        #pragma unroll
        for (int c0=0;c0<48;c0+=4){
            float a0=bsn[c0+0], a1=bsn[c0+1], a2=bsn[c0+2], a3=bsn[c0+3];
            #pragma unroll
            for (int e=0;e<16;e++){
                float fe = f[e];
                float4 w = *(const float4*)&WTn[e*48+c0];
                a0=fmaf(fe,w.x,a0); a1=fmaf(fe,w.y,a1); a2=fmaf(fe,w.z,a2); a3=fmaf(fe,w.w,a3);
            }
            float4 v4 = make_float4(a0,a1,a2,a3);
            if (c0 < 16){
                ((float4*)(g_q + row*16))[c0>>2] = v4;
            } else if (c0 < 32){
                int hh = (c0-16)>>2;
                ((float4*)g_K)[((l+1)*BB+b)*HH*LMAX + hh*LMAX + i] = v4;
            } else {
                int hh = (c0-32)>>2;
                ((float4*)g_V)[((l+1)*BB+b)*HH*LMAX + hh*LMAX + i] = v4;
            }
        }
    }
}

// ---------------- decode: K/V + weights in smem, LDS staging (unchanged) ----------------
#define DEC_WFLOATS (3072+1024+4096+4096+192+64*8+256+64+64+64+256)
#define DEC_SMEM (9600*16 + (32+DEC_WFLOATS)*4)

__global__ void decode_kernel(const float* __restrict__ bqkv, const float* __restrict__ bo,
    const float* __restrict__ crossb,
    const float* __restrict__ l1g, const float* __restrict__ l1b,
    const float* __restrict__ l2g, const float* __restrict__ l2b,
    const float* __restrict__ l3g, const float* __restrict__ l3b,
    const float* __restrict__ fb1, const float* __restrict__ fb2,
    const float* __restrict__ pe,  const float* __restrict__ outW,
    const float* __restrict__ outb, float* __restrict__ out){
    extern __shared__ float4 sm4[];
    float4* K4   = sm4;              // [l][h][p]
    float4* V4   = sm4 + 4800;
    float*  atts = (float*)(sm4 + 9600);   // [2][16]
    float*  sWq  = atts + 32;
    float*  sWo  = sWq + 3072;
    float*  sW1  = sWo + 1024;
    float*  sW2  = sW1 + 4096;
    float*  sBq  = sW2 + 4096;
    float*  sBo  = sBq + 192;
    float*  sCb  = sBo + 64;
    float*  sG1  = sCb + 64;
    float*  sB1  = sG1 + 64;
    float*  sG2  = sB1 + 64;
    float*  sB2  = sG2 + 64;
    float*  sG3  = sB2 + 64;
    float*  sB3  = sG3 + 64;
    float*  sF1  = sB3 + 64;
    float*  sF2  = sF1 + 256;
    float*  xbuf = sF2 + 64;    // [4][16]
    float*  zbuf = xbuf + 64;   // [4][16]
    float*  hbuf = zbuf + 64;   // [4][64]
    int tid  = threadIdx.x;  // 128
    int lane = tid & 31, wh = tid >> 5;
    int b    = blockIdx.x;

    for (int i=tid;i<4608;i+=128){
        int l = i/1152, r = i%1152, h = r/288, pp = r%288;
        int dst = (l*4+h)*300 + pp;
        int src = ((l*64+b)*4+h)*300 + pp;
        K4[dst] = ((const float4*)g_K)[src];
        V4[dst] = ((const float4*)g_V)[src];
    }
    for (int i=tid;i<3072;i+=128) sWq[i] = g_WqT[i];
    for (int i=tid;i<1024;i+=128) sWo[i] = g_WoT[i];
    for (int i=tid;i<4096;i+=128) sW1[i] = g_W1T[i];
    for (int i=tid;i<4096;i+=128) sW2[i] = g_W2T[i];
    for (int i=tid;i<192;i+=128)  sBq[i] = bqkv[i];
    if (tid<64){
        sBo[tid]=bo[tid]; sCb[tid]=crossb[tid];
        sG1[tid]=l1g[tid]; sB1[tid]=l1b[tid];
        sG2[tid]=l2g[tid]; sB2[tid]=l2b[tid];
        sG3[tid]=l3g[tid]; sB3[tid]=l3b[tid];
        sF2[tid]=fb2[tid];
    }
    for (int i=tid;i<256;i+=128) sF1[i] = fb1[i];

    int d = lane & 15;
    float oW = outW[d];
    float w2s = gsum16f(oW*oW);
    float ob  = outb[0];
    float x = g_x[(b*TC + TC-1)*DD + d];
    float nt = gsum16f(x*oW) + ob;
    if (tid==0) out[b*TF+0] = fmaf(nt, w2s, ob);
    x = fmaf(nt, oW, pe[TC*DD + d]);
    if (lane < 16) xbuf[wh*16+d] = x;
    __syncthreads();

    int it = 0;
    for (int t=1;t<TF;t++){
        int p = TC - 1 + t;
        for (int l=0;l<NLAY;l++){
            int li = (lane < 12) ? lane : 11;
            int dd = li & 3;
            int c  = (li<4) ? wh*4+dd : ((li<8) ? 16+wh*4+dd : 32+wh*4+dd);
            float acc = sBq[l*48+c];
            const float* wq = sWq + l*768 + c;
            const float* xb = xbuf + wh*16;
            #pragma unroll
            for (int e=0;e<16;e++) acc = fmaf(xb[e], wq[e*48], acc);
            int base = ((l*4+wh)*300 + p)*4;
            if (lane>=4 && lane<8)  ((float*)K4)[base + (lane-4)] = acc;
            if (lane>=8 && lane<12) ((float*)V4)[base + (lane-8)] = acc;
            __syncwarp();
            float q0 = __shfl_sync(FULL, acc, 0);
            float q1 = __shfl_sync(FULL, acc, 1);
            float q2 = __shfl_sync(FULL, acc, 2);
            float q3 = __shfl_sync(FULL, acc, 3);
            const float4* Kh = K4 + (l*4+wh)*300;
            const float4* Vh = V4 + (l*4+wh)*300;
            float s=0.f, o0=0.f, o1=0.f, o2=0.f, o3=0.f;
            for (int j=lane;j<=p;j+=32){
                float4 k4 = Kh[j];
                float sc = (k4.x*q0 + k4.y*q1 + k4.z*q2 + k4.w*q3) * 0.5f;
                float pr = __expf(sc);
                float4 v4 = Vh[j];
                s += pr;
                o0 = fmaf(pr, v4.x, o0); o1 = fmaf(pr, v4.y, o1);
                o2 = fmaf(pr, v4.z, o2); o3 = fmaf(pr, v4.w, o3);
            }
            #pragma unroll
            for (int off=16;off>0;off>>=1){
                s  += __shfl_xor_sync(FULL, s,  off);
                o0 += __shfl_xor_sync(FULL, o0, off);
                o1 += __shfl_xor_sync(FULL, o1, off);
                o2 += __shfl_xor_sync(FULL, o2, off);
                o3 += __shfl_xor_sync(FULL, o3, off);
            }
            float* ab = atts + (it&1)*16;
            if (lane==0){
                float inv = 1.f/s;
                ab[wh*4+0]=o0*inv; ab[wh*4+1]=o1*inv;
                ab[wh*4+2]=o2*inv; ab[wh*4+3]=o3*inv;
            }
            __syncthreads();
            float a = sBo[l*16+d] + x;
            const float* wo = sWo + l*256 + d;
            #pragma unroll
            for (int e=0;e<16;e++) a = fmaf(ab[e], wo[e*16], a);
            a = lnorm16s(a, sG1[l*16+d], sB1[l*16+d]);
            a += sCb[l*16+d];
            float z = lnorm16s(a, sG2[l*16+d], sB2[l*16+d]);
            if (lane < 16) zbuf[wh*16+d] = z;
            __syncwarp();
            const float* zb = zbuf + wh*16;
            const float* w1 = sW1 + l*1024;
            float hv0=sF1[l*64+d], hv1=sF1[l*64+16+d], hv2=sF1[l*64+32+d], hv3=sF1[l*64+48+d];
            #pragma unroll
            for (int e=0;e<16;e++){
                float ze = zb[e];
                hv0 = fmaf(ze, w1[e*64 +      d], hv0);
                hv1 = fmaf(ze, w1[e*64 + 16 + d], hv1);
                hv2 = fmaf(ze, w1[e*64 + 32 + d], hv2);
                hv3 = fmaf(ze, w1[e*64 + 48 + d], hv3);
            }
            hv0=fmaxf(hv0,0.f); hv1=fmaxf(hv1,0.f); hv2=fmaxf(hv2,0.f); hv3=fmaxf(hv3,0.f);
            if (lane < 16){
                hbuf[wh*64 +      d] = hv0;
                hbuf[wh*64 + 16 + d] = hv1;
                hbuf[wh*64 + 32 + d] = hv2;
                hbuf[wh*64 + 48 + d] = hv3;
            }
            __syncwarp();
            const float* hb = hbuf + wh*64;
            const float* w2 = sW2 + l*1024;
            float f0 = sF2[l*16+d] + z, f1=0.f, f2=0.f, f3=0.f;
            #pragma unroll
            for (int e=0;e<16;e++){
                f0 = fmaf(hb[     e], w2[( 0+e)*16+d], f0);
                f1 = fmaf(hb[16 + e], w2[(16+e)*16+d], f1);
                f2 = fmaf(hb[32 + e], w2[(32+e)*16+d], f2);
                f3 = fmaf(hb[48 + e], w2[(48+e)*16+d], f3);
            }
            float f = lnorm16s((f0+f1)+(f2+f3), sG3[l*16+d], sB3[l*16+d]);
            if (l < NLAY-1){
                x = f;
            } else {
                float nv = gsum16f(f*oW) + ob;
                if (tid==0) out[b*TF+t] = fmaf(nv, w2s, ob);
                x = fmaf(nv, oW, pe[(p+1)*DD + d]);
            }
            if (lane < 16) xbuf[wh*16+d] = x;
            __syncwarp();
            it++;
        }
    }
}

// ---------------- launch ----------------
extern "C" void kernel_launch(void* const* d_in, const int* in_sizes, int n_in,
                              void* d_out, int out_size){
    const float* b1     = (const float*)d_in[0];
    const float* b2     = (const float*)d_in[1];
    const float* b3     = (const float*)d_in[2];
    const float* fW     = (const float*)d_in[3];
    const float* fb     = (const float*)d_in[4];
    const float* pe     = (const float*)d_in[5];
    const float* Wqkv   = (const float*)d_in[6];
    const float* bqkv   = (const float*)d_in[7];
    const float* Wo     = (const float*)d_in[8];
    const float* bo     = (const float*)d_in[9];
    const float* crossb = (const float*)d_in[10];
    const float* l1g    = (const float*)d_in[11];
    const float* l1b    = (const float*)d_in[12];
    const float* l2g    = (const float*)d_in[13];
    const float* l2b    = (const float*)d_in[14];
    const float* l3g    = (const float*)d_in[15];
    const float* l3b    = (const float*)d_in[16];
    const float* fW1    = (const float*)d_in[17];
    const float* fb1    = (const float*)d_in[18];
    const float* fW2    = (const float*)d_in[19];
    const float* fb2    = (const float*)d_in[20];
    const float* outW   = (const float*)d_in[21];
    const float* outb   = (const float*)d_in[22];
    float* out = (float*)d_out;

    static int smem_set = 0;
    if (!smem_set){
        cudaFuncSetAttribute(decode_kernel, cudaFuncAttributeMaxDynamicSharedMemorySize, DEC_SMEM);
        smem_set = 1;
    }

    prep_kernel<<<12,256>>>(Wqkv, Wo, fW1, fW2);
    fuse_kernel<<<1152,256>>>(b1, b2, b3, fW, fb, pe, bqkv);
    for (int l=0;l<NLAY;l++){
        attn_kernel<<<BB*HH,576>>>(l);
        post_kernel<<<144,128>>>(l, bo, crossb, l1g,l1b,l2g,l2b,l3g,l3b, fb1, fb2, bqkv);
    }
    decode_kernel<<<BB,128,DEC_SMEM>>>(bqkv, bo, crossb, l1g,l1b,l2g,l2b,l3g,l3b,
                                       fb1, fb2, pe, outW, outb, out);
}

// round 13
// speedup vs baseline: 1.0894x; 1.0894x over previous
#include <cuda_runtime.h>

#define BB    64
#define TC    288
#define TF    12
#define LMAX  300
#define DD    16
#define HH    4
#define HDIM  4
#define DFF   64
#define NLAY  4
#define FULL  0xffffffffu

// ---------------- device scratch ----------------
__device__ float g_x  [BB*TC*DD];
__device__ float g_q  [BB*TC*DD];
__device__ float g_att[BB*TC*DD];
__device__ float g_K  [NLAY*BB*HH*LMAX*HDIM];
__device__ float g_V  [NLAY*BB*HH*LMAX*HDIM];
__device__ float g_WqT[NLAY*768];            // [l][e][c]   e*48+c
__device__ float g_WoT[NLAY*256];            // [l][e][d]   e*16+d
__device__ float g_W1T[NLAY*1024];           // [l][e][j]   e*64+j
__device__ float g_W2T[NLAY*1024];           // [l][j][d]   j*16+d

__device__ __forceinline__ int kidx(int l,int b,int h,int p,int d){
    return (((l*BB+b)*HH+h)*LMAX+p)*HDIM+d;
}

__device__ __forceinline__ float gsum16f(float v){
    v += __shfl_xor_sync(FULL, v, 8, 16);
    v += __shfl_xor_sync(FULL, v, 4, 16);
    v += __shfl_xor_sync(FULL, v, 2, 16);
    v += __shfl_xor_sync(FULL, v, 1, 16);
    return v;
}
__device__ __forceinline__ float lnorm16s(float v, float g, float b){
    float s1 = v, s2 = v*v;
    #pragma unroll
    for (int o=8;o>0;o>>=1){
        s1 += __shfl_xor_sync(FULL, s1, o, 16);
        s2 += __shfl_xor_sync(FULL, s2, o, 16);
    }
    float mu  = s1 * 0.0625f;
    float var = fmaf(s2, 0.0625f, -mu*mu);
    return (v - mu) * rsqrtf(var + 1e-5f) * g + b;
}

// ---------------- weight transpose prep ----------------
__global__ void prep_kernel(const float* __restrict__ Wqkv, const float* __restrict__ Wo,
                            const float* __restrict__ fW1,  const float* __restrict__ fW2){
    int tid = blockIdx.x*blockDim.x + threadIdx.x;
    int str = gridDim.x*blockDim.x;
    for (int i=tid;i<NLAY*768;i+=str){ int l=i/768, r=i%768, e=r/48, c=r%48;
        g_WqT[i] = Wqkv[(l*48+c)*16+e]; }
    for (int i=tid;i<NLAY*256;i+=str){ int l=i/256, r=i%256, e=r/16, d=r%16;
        g_WoT[i] = Wo[(l*16+d)*16+e]; }
    for (int i=tid;i<NLAY*1024;i+=str){ int l=i/1024, r=i%1024, e=r/64, j=r%64;
        g_W1T[i] = fW1[(l*64+j)*16+e]; }
    for (int i=tid;i<NLAY*1024;i+=str){ int l=i/1024, r=i%1024, j=r/16, d=r%16;
        g_W2T[i] = fW2[(l*16+d)*64+j]; }
}

// ---------------- fusion + layer-0 QKV ----------------
__global__ void fuse_kernel(const float* __restrict__ b1, const float* __restrict__ b2,
                            const float* __restrict__ b3, const float* __restrict__ fW,
                            const float* __restrict__ fb, const float* __restrict__ pe,
                            const float* __restrict__ bqkv){
    __shared__ __align__(16) float WfT[768];
    __shared__ __align__(16) float WT[768];
    __shared__ float fbs[16], bs[48];
    int tid = threadIdx.x;       // 256
    for (int i=tid;i<768;i+=256){ int e=i>>4, d=i&15; WfT[i] = fW[d*48+e]; }
    for (int i=tid;i<768;i+=256) WT[i] = g_WqT[i];
    if (tid<16) fbs[tid] = fb[tid];
    if (tid<48) bs[tid]  = bqkv[tid];
    __syncthreads();
    int idx = blockIdx.x*256 + tid;
    int row = idx >> 4, d = idx & 15;
    int i   = row % TC;
    int b   = row / TC;
    const float* r1 = b1 + row*16;
    const float* r2 = b2 + row*16;
    const float* r3 = b3 + row*16;
    float acc = fbs[d];
    #pragma unroll
    for (int e=0;e<16;e++) acc = fmaf(r1[e], WfT[e*16+d],      acc);
    #pragma unroll
    for (int e=0;e<16;e++) acc = fmaf(r2[e], WfT[(16+e)*16+d], acc);
    #pragma unroll
    for (int e=0;e<16;e++) acc = fmaf(r3[e], WfT[(32+e)*16+d], acc);
    acc += pe[i*16+d];
    g_x[idx] = acc;
    float aq=bs[d], ak=bs[16+d], av=bs[32+d];
    #pragma unroll
    for (int e=0;e<16;e++){
        float xe = __shfl_sync(FULL, acc, e, 16);
        aq = fmaf(xe, WT[e*48+d],    aq);
        ak = fmaf(xe, WT[e*48+16+d], ak);
        av = fmaf(xe, WT[e*48+32+d], av);
    }
    g_q[row*16+d] = aq;
    g_K[kidx(0,b,d>>2,i,d&3)] = ak;
    g_V[kidx(0,b,d>>2,i,d&3)] = av;
}

// ---------------- prefill attention: 2 threads per row (key split) ----------------
__global__ void attn_kernel(int l){
    __shared__ float4 ks4[TC], vs4[TC];
    int b = blockIdx.x >> 2, h = blockIdx.x & 3;
    int tid = threadIdx.x;   // 576
    const float4* Kb = (const float4*)(g_K + kidx(l,b,h,0,0));
    const float4* Vb = (const float4*)(g_V + kidx(l,b,h,0,0));
    for (int i=tid;i<TC;i+=576){ ks4[i]=Kb[i]; vs4[i]=Vb[i]; }
    __syncthreads();
    int i = tid >> 1;        // row
    int u = tid & 1;         // key-parity half
    float4 qv = ((const float4*)g_q)[(b*TC+i)*4 + h];
    float q0=qv.x, q1=qv.y, q2=qv.z, q3=qv.w;
    float s=0.f, o0=0.f, o1=0.f, o2=0.f, o3=0.f;
    int jend = min(i|15, TC-1);          // warp-uniform (16 rows per warp)
    for (int j=u;j<=jend;j+=2){
        float4 k4 = ks4[j];
        float sc = (k4.x*q0 + k4.y*q1 + k4.z*q2 + k4.w*q3) * 0.5f;
        float p  = __expf(sc);
        p = (j <= i) ? p : 0.f;
        float4 v4 = vs4[j];
        s += p;
        o0 = fmaf(p, v4.x, o0); o1 = fmaf(p, v4.y, o1);
        o2 = fmaf(p, v4.z, o2); o3 = fmaf(p, v4.w, o3);
    }
    s  += __shfl_xor_sync(FULL, s,  1);
    o0 += __shfl_xor_sync(FULL, o0, 1);
    o1 += __shfl_xor_sync(FULL, o1, 1);
    o2 += __shfl_xor_sync(FULL, o2, 1);
    o3 += __shfl_xor_sync(FULL, o3, 1);
    if (u==0){
        float inv = 1.0f/s;
        float4 r; r.x=o0*inv; r.y=o1*inv; r.z=o2*inv; r.w=o3*inv;
        ((float4*)g_att)[(b*TC+i)*4 + h] = r;
    }
}

// ---------------- post: 2 threads per row (R11 best-measured) ----------------
#define ZSTR 17
#define HSTR 68
__global__ void post_kernel(int l, const float* __restrict__ bo, const float* __restrict__ crossb,
    const float* __restrict__ l1g, const float* __restrict__ l1b,
    const float* __restrict__ l2g, const float* __restrict__ l2b,
    const float* __restrict__ l3g, const float* __restrict__ l3b,
    const float* __restrict__ fb1, const float* __restrict__ fb2,
    const float* __restrict__ bqkv){
    __shared__ __align__(16) float WoT[256], W1T[1024], W2T[1024], WTn[768];
    __shared__ float bos[16], cbs[16], g1[16], bb1[16], g2[16], bb2[16], g3[16], bb3[16];
    __shared__ float fb1s[64], fb2s[16], bsn[48];
    __shared__ float zrow[64*ZSTR];
    __shared__ __align__(16) float hrow[64*HSTR];
    __shared__ float frow[64*ZSTR];
    int tid = threadIdx.x;   // 128 -> 64 rows per block
    for (int i=tid;i<256;i+=128)  WoT[i] = g_WoT[l*256+i];
    for (int i=tid;i<1024;i+=128) W1T[i] = g_W1T[l*1024+i];
    for (int i=tid;i<1024;i+=128) W2T[i] = g_W2T[l*1024+i];
    if (l < NLAY-1){
        for (int i=tid;i<768;i+=128) WTn[i] = g_WqT[(l+1)*768+i];
        if (tid<48) bsn[tid] = bqkv[(l+1)*48+tid];
    }
    if (tid<16){
        bos[tid]=bo[l*16+tid]; cbs[tid]=crossb[l*16+tid];
        g1[tid]=l1g[l*16+tid]; bb1[tid]=l1b[l*16+tid];
        g2[tid]=l2g[l*16+tid]; bb2[tid]=l2b[l*16+tid];
        g3[tid]=l3g[l*16+tid]; bb3[tid]=l3b[l*16+tid];
        fb2s[tid]=fb2[l*16+tid];
    }
    if (tid<64) fb1s[tid]=fb1[l*64+tid];
    __syncthreads();
    int u    = tid & 1;
    int lrow = tid >> 1;
    int row  = blockIdx.x*64 + lrow;   // grid 288
    int b = row / TC, i = row % TC;
    int off = u*8;

    float att[16];
    {
        const float4* ar = (const float4*)(g_att + row*16);
        #pragma unroll
        for (int k=0;k<4;k++){
            float4 av = ar[k];
            att[k*4+0]=av.x; att[k*4+1]=av.y; att[k*4+2]=av.z; att[k*4+3]=av.w;
        }
    }
    float a[8];
    {
        const float4* xr = (const float4*)(g_x + row*16);
        float4 x0 = xr[u*2+0], x1 = xr[u*2+1];
        a[0]=x0.x; a[1]=x0.y; a[2]=x0.z; a[3]=x0.w;
        a[4]=x1.x; a[5]=x1.y; a[6]=x1.z; a[7]=x1.w;
    }
    #pragma unroll
    for (int k=0;k<8;k++) a[k] += bos[off+k];
    #pragma unroll
    for (int e=0;e<16;e++){
        float ae = att[e];
        #pragma unroll
        for (int k=0;k<2;k++){
            float4 w = *(const float4*)&WoT[e*16+off+k*4];
            a[k*4+0]=fmaf(ae,w.x,a[k*4+0]); a[k*4+1]=fmaf(ae,w.y,a[k*4+1]);
            a[k*4+2]=fmaf(ae,w.z,a[k*4+2]); a[k*4+3]=fmaf(ae,w.w,a[k*4+3]);
        }
    }
    {
        float s1=0.f,s2=0.f;
        #pragma unroll
        for (int k=0;k<8;k++){ s1+=a[k]; s2=fmaf(a[k],a[k],s2); }
        s1 += __shfl_xor_sync(FULL,s1,1); s2 += __shfl_xor_sync(FULL,s2,1);
        float mu=s1*0.0625f, rstd=rsqrtf(fmaf(s2,0.0625f,-mu*mu)+1e-5f);
        #pragma unroll
        for (int k=0;k<8;k++) a[k] = (a[k]-mu)*rstd*g1[off+k] + bb1[off+k] + cbs[off+k];
    }
    {
        float s1=0.f,s2=0.f;
        #pragma unroll
        for (int k=0;k<8;k++){ s1+=a[k]; s2=fmaf(a[k],a[k],s2); }
        s1 += __shfl_xor_sync(FULL,s1,1); s2 += __shfl_xor_sync(FULL,s2,1);
        float mu=s1*0.0625f, rstd=rsqrtf(fmaf(s2,0.0625f,-mu*mu)+1e-5f);
        #pragma unroll
        for (int k=0;k<8;k++) a[k] = (a[k]-mu)*rstd*g2[off+k] + bb2[off+k];
    }
    #pragma unroll
    for (int k=0;k<8;k++) zrow[lrow*ZSTR+off+k] = a[k];
    __syncwarp();
    float zf[16];
    #pragma unroll
    for (int m=0;m<16;m++) zf[m] = zrow[lrow*ZSTR+m];
    float h[32];
    #pragma unroll
    for (int jj=0;jj<32;jj++) h[jj] = fb1s[u*32+jj];
    #pragma unroll
    for (int e=0;e<16;e++){
        float ze = zf[e];
        const float* w1 = &W1T[e*64 + u*32];
        #pragma unroll
        for (int jj=0;jj<32;jj++) h[jj] = fmaf(ze, w1[jj], h[jj]);
    }
    #pragma unroll
    for (int jj=0;jj<32;jj++) h[jj] = fmaxf(h[jj], 0.f);
    {
        float4* hw = (float4*)&hrow[lrow*HSTR + u*32];
        #pragma unroll
        for (int k=0;k<8;k++) hw[k] = make_float4(h[k*4+0],h[k*4+1],h[k*4+2],h[k*4+3]);
    }
    __syncwarp();
    float f[8];
    #pragma unroll
    for (int k=0;k<8;k++) f[k] = fb2s[off+k] + zf[off+k];
    const float* hb = &hrow[lrow*HSTR];
    #pragma unroll
    for (int j=0;j<64;j++){
        float hj = hb[j];
        #pragma unroll
        for (int k=0;k<8;k++) f[k] = fmaf(hj, W2T[j*16+off+k], f[k]);
    }
    {
        float s1=0.f,s2=0.f;
        #pragma unroll
        for (int k=0;k<8;k++){ s1+=f[k]; s2=fmaf(f[k],f[k],s2); }
        s1 += __shfl_xor_sync(FULL,s1,1); s2 += __shfl_xor_sync(FULL,s2,1);
        float mu=s1*0.0625f, rstd=rsqrtf(fmaf(s2,0.0625f,-mu*mu)+1e-5f);
        #pragma unroll
        for (int k=0;k<8;k++) f[k] = (f[k]-mu)*rstd*g3[off+k] + bb3[off+k];
    }
    {
        float4* xw = (float4*)(g_x + row*16 + off);
        xw[0] = make_float4(f[0],f[1],f[2],f[3]);
        xw[1] = make_float4(f[4],f[5],f[6],f[7]);
    }
    if (l < NLAY-1){
        #pragma unroll
        for (int k=0;k<8;k++) frow[lrow*ZSTR+off+k] = f[k];
        __syncwarp();
        float ff[16];
        #pragma unroll
        for (int m=0;m<16;m++) ff[m] = frow[lrow*ZSTR+m];
        int c0base = u*24;
        #pragma unroll
        for (int c0=0;c0<24;c0+=4){
            int c = c0base + c0;
            float a0=bsn[c+0], a1=bsn[c+1], a2=bsn[c+2], a3=bsn[c+3];
            #pragma unroll
            for (int e=0;e<16;e++){
                float fe = ff[e];
                float4 w = *(const float4*)&WTn[e*48+c];
                a0=fmaf(fe,w.x,a0); a1=fmaf(fe,w.y,a1); a2=fmaf(fe,w.z,a2); a3=fmaf(fe,w.w,a3);
            }
            float4 v4 = make_float4(a0,a1,a2,a3);
            if (c < 16){
                ((float4*)(g_q + row*16))[c>>2] = v4;
            } else if (c < 32){
                int hh = (c-16)>>2;
                ((float4*)g_K)[((l+1)*BB+b)*HH*LMAX + hh*LMAX + i] = v4;
            } else {
                int hh = (c-32)>>2;
                ((float4*)g_V)[((l+1)*BB+b)*HH*LMAX + hh*LMAX + i] = v4;
            }
        }
    }
}

// ---------------- decode: full-warp work split (both half-warps productive) ----------------
#define DEC_WFLOATS (3072+1024+4096+4096+192+64*8+256+64+64+64+256)
#define DEC_SMEM (9600*16 + (32+DEC_WFLOATS)*4)

__global__ void decode_kernel(const float* __restrict__ bqkv, const float* __restrict__ bo,
    const float* __restrict__ crossb,
    const float* __restrict__ l1g, const float* __restrict__ l1b,
    const float* __restrict__ l2g, const float* __restrict__ l2b,
    const float* __restrict__ l3g, const float* __restrict__ l3b,
    const float* __restrict__ fb1, const float* __restrict__ fb2,
    const float* __restrict__ pe,  const float* __restrict__ outW,
    const float* __restrict__ outb, float* __restrict__ out){
    extern __shared__ float4 sm4[];
    float4* K4   = sm4;              // [l][h][p]
    float4* V4   = sm4 + 4800;
    float*  atts = (float*)(sm4 + 9600);   // [2][16]
    float*  sWq  = atts + 32;
    float*  sWo  = sWq + 3072;
    float*  sW1  = sWo + 1024;
    float*  sW2  = sW1 + 4096;
    float*  sBq  = sW2 + 4096;
    float*  sBo  = sBq + 192;
    float*  sCb  = sBo + 64;
    float*  sG1  = sCb + 64;
    float*  sB1  = sG1 + 64;
    float*  sG2  = sB1 + 64;
    float*  sB2  = sG2 + 64;
    float*  sG3  = sB2 + 64;
    float*  sB3  = sG3 + 64;
    float*  sF1  = sB3 + 64;
    float*  sF2  = sF1 + 256;
    float*  xbuf = sF2 + 64;    // [4][16]
    float*  zbuf = xbuf + 64;   // [4][16]
    float*  hbuf = zbuf + 64;   // [4][64]
    int tid  = threadIdx.x;  // 128
    int lane = tid & 31, wh = tid >> 5;
    int half = lane >> 4;    // 0/1
    int b    = blockIdx.x;

    for (int i=tid;i<4608;i+=128){
        int l = i/1152, r = i%1152, h = r/288, pp = r%288;
        int dst = (l*4+h)*300 + pp;
        int src = ((l*64+b)*4+h)*300 + pp;
        K4[dst] = ((const float4*)g_K)[src];
        V4[dst] = ((const float4*)g_V)[src];
    }
    for (int i=tid;i<3072;i+=128) sWq[i] = g_WqT[i];
    for (int i=tid;i<1024;i+=128) sWo[i] = g_WoT[i];
    for (int i=tid;i<4096;i+=128) sW1[i] = g_W1T[i];
    for (int i=tid;i<4096;i+=128) sW2[i] = g_W2T[i];
    for (int i=tid;i<192;i+=128)  sBq[i] = bqkv[i];
    if (tid<64){
        sBo[tid]=bo[tid]; sCb[tid]=crossb[tid];
        sG1[tid]=l1g[tid]; sB1[tid]=l1b[tid];
        sG2[tid]=l2g[tid]; sB2[tid]=l2b[tid];
        sG3[tid]=l3g[tid]; sB3[tid]=l3b[tid];
        sF2[tid]=fb2[tid];
    }
    for (int i=tid;i<256;i+=128) sF1[i] = fb1[i];

    int d = lane & 15;
    float oW = outW[d];
    float w2s = gsum16f(oW*oW);
    float ob  = outb[0];
    float x = g_x[(b*TC + TC-1)*DD + d];
    float nt = gsum16f(x*oW) + ob;
    if (tid==0) out[b*TF+0] = fmaf(nt, w2s, ob);
    x = fmaf(nt, oW, pe[TC*DD + d]);
    if (lane < 16) xbuf[wh*16+d] = x;
    __syncthreads();

    int it = 0;
    for (int t=1;t<TF;t++){
        int p = TC - 1 + t;
        for (int l=0;l<NLAY;l++){
            // qkv: e-split across halves, combined via shfl_xor(16)
            int lq = lane & 15;
            int li = (lq < 12) ? lq : 11;
            int dd = li & 3;
            int c  = (li<4) ? wh*4+dd : ((li<8) ? 16+wh*4+dd : 32+wh*4+dd);
            float acc = half ? 0.f : sBq[l*48+c];
            const float* wq = sWq + l*768 + c;
            const float* xb = xbuf + wh*16;
            int e0 = half*8;
            #pragma unroll
            for (int e=0;e<8;e++) acc = fmaf(xb[e0+e], wq[(e0+e)*48], acc);
            acc += __shfl_xor_sync(FULL, acc, 16);
            int base = ((l*4+wh)*300 + p)*4;
            if (lane>=4 && lane<8)  ((float*)K4)[base + (lane-4)] = acc;
            if (lane>=8 && lane<12) ((float*)V4)[base + (lane-8)] = acc;
            __syncwarp();
            float q0 = __shfl_sync(FULL, acc, 0);
            float q1 = __shfl_sync(FULL, acc, 1);
            float q2 = __shfl_sync(FULL, acc, 2);
            float q3 = __shfl_sync(FULL, acc, 3);
            const float4* Kh = K4 + (l*4+wh)*300;
            const float4* Vh = V4 + (l*4+wh)*300;
            float s=0.f, o0=0.f, o1=0.f, o2=0.f, o3=0.f;
            for (int j=lane;j<=p;j+=32){
                float4 k4 = Kh[j];
                float sc = (k4.x*q0 + k4.y*q1 + k4.z*q2 + k4.w*q3) * 0.5f;
                float pr = __expf(sc);
                float4 v4 = Vh[j];
                s += pr;
                o0 = fmaf(pr, v4.x, o0); o1 = fmaf(pr, v4.y, o1);
                o2 = fmaf(pr, v4.z, o2); o3 = fmaf(pr, v4.w, o3);
            }
            #pragma unroll
            for (int off=16;off>0;off>>=1){
                s  += __shfl_xor_sync(FULL, s,  off);
                o0 += __shfl_xor_sync(FULL, o0, off);
                o1 += __shfl_xor_sync(FULL, o1, off);
                o2 += __shfl_xor_sync(FULL, o2, off);
                o3 += __shfl_xor_sync(FULL, o3, off);
            }
            float* ab = atts + (it&1)*16;
            if (lane==0){
                float inv = 1.f/s;
                ab[wh*4+0]=o0*inv; ab[wh*4+1]=o1*inv;
                ab[wh*4+2]=o2*inv; ab[wh*4+3]=o3*inv;
            }
            __syncthreads();   // only block barrier per layer
            // out-proj: e-split across halves
            const float* wo = sWo + l*256 + d;
            float ap = 0.f;
            #pragma unroll
            for (int e=0;e<8;e++) ap = fmaf(ab[e0+e], wo[(e0+e)*16], ap);
            ap += __shfl_xor_sync(FULL, ap, 16);
            float a = sBo[l*16+d] + x + ap;
            a = lnorm16s(a, sG1[l*16+d], sB1[l*16+d]);
            a += sCb[l*16+d];
            float z = lnorm16s(a, sG2[l*16+d], sB2[l*16+d]);
            if (lane < 16) zbuf[wh*16+d] = z;
            __syncwarp();
            const float* zb = zbuf + wh*16;
            // FFN1: half h computes hidden j0=h*16+d and j0+32 (bank-conflict-free)
            const float* w1 = sW1 + l*1024;
            int j0 = half*16 + d;
            float hv0 = sF1[l*64+j0], hv1 = sF1[l*64+j0+32];
            #pragma unroll
            for (int e=0;e<16;e++){
                float ze = zb[e];
                hv0 = fmaf(ze, w1[e*64 + j0],      hv0);
                hv1 = fmaf(ze, w1[e*64 + j0 + 32], hv1);
            }
            hv0 = fmaxf(hv0, 0.f); hv1 = fmaxf(hv1, 0.f);
            hbuf[wh*64 + j0]      = hv0;
            hbuf[wh*64 + j0 + 32] = hv1;
            __syncwarp();
            // FFN2: j-parity split across halves, combined via shfl_xor(16)
            const float* hb = hbuf + wh*64;
            const float* w2 = sW2 + l*1024;
            float fp0 = 0.f, fp1 = 0.f;
            #pragma unroll
            for (int jj=0;jj<16;jj++){
                int ja = jj*4 + half;        // half0: 0,4,8..  half1: 1,5,9..
                int jb = jj*4 + 2 + half;    // half0: 2,6..    half1: 3,7..
                fp0 = fmaf(hb[ja], w2[ja*16+d], fp0);
                fp1 = fmaf(hb[jb], w2[jb*16+d], fp1);
            }
            float fp = fp0 + fp1;
            fp += __shfl_xor_sync(FULL, fp, 16);
            float f = lnorm16s(sF2[l*16+d] + z + fp, sG3[l*16+d], sB3[l*16+d]);
            if (l < NLAY-1){
                x = f;
            } else {
                float nv = gsum16f(f*oW) + ob;
                if (tid==0) out[b*TF+t] = fmaf(nv, w2s, ob);
                x = fmaf(nv, oW, pe[(p+1)*DD + d]);
            }
            if (lane < 16) xbuf[wh*16+d] = x;
            __syncwarp();
            it++;
        }
    }
}

// ---------------- launch ----------------
extern "C" void kernel_launch(void* const* d_in, const int* in_sizes, int n_in,
                              void* d_out, int out_size){
    const float* b1     = (const float*)d_in[0];
    const float* b2     = (const float*)d_in[1];
    const float* b3     = (const float*)d_in[2];
    const float* fW     = (const float*)d_in[3];
    const float* fb     = (const float*)d_in[4];
    const float* pe     = (const float*)d_in[5];
    const float* Wqkv   = (const float*)d_in[6];
    const float* bqkv   = (const float*)d_in[7];
    const float* Wo     = (const float*)d_in[8];
    const float* bo     = (const float*)d_in[9];
    const float* crossb = (const float*)d_in[10];
    const float* l1g    = (const float*)d_in[11];
    const float* l1b    = (const float*)d_in[12];
    const float* l2g    = (const float*)d_in[13];
    const float* l2b    = (const float*)d_in[14];
    const float* l3g    = (const float*)d_in[15];
    const float* l3b    = (const float*)d_in[16];
    const float* fW1    = (const float*)d_in[17];
    const float* fb1    = (const float*)d_in[18];
    const float* fW2    = (const float*)d_in[19];
    const float* fb2    = (const float*)d_in[20];
    const float* outW   = (const float*)d_in[21];
    const float* outb   = (const float*)d_in[22];
    float* out = (float*)d_out;

    static int smem_set = 0;
    if (!smem_set){
        cudaFuncSetAttribute(decode_kernel, cudaFuncAttributeMaxDynamicSharedMemorySize, DEC_SMEM);
        smem_set = 1;
    }

    prep_kernel<<<12,256>>>(Wqkv, Wo, fW1, fW2);
    fuse_kernel<<<1152,256>>>(b1, b2, b3, fW, fb, pe, bqkv);
    for (int l=0;l<NLAY;l++){
        attn_kernel<<<BB*HH,576>>>(l);
        post_kernel<<<288,128>>>(l, bo, crossb, l1g,l1b,l2g,l2b,l3g,l3b, fb1, fb2, bqkv);
    }
    decode_kernel<<<BB,128,DEC_SMEM>>>(bqkv, bo, crossb, l1g,l1b,l2g,l2b,l3g,l3b,
                                       fb1, fb2, pe, outW, outb, out);
}